// round 10
// baseline (speedup 1.0000x reference)
#include <cuda_runtime.h>
#include <cuda_bf16.h>
#include <cstdint>
#include <cstddef>

// ---------------------------------------------------------------------------
// Decoder: out = (x - diag(t_mlp(z))) * exp(-diag(s_mlp(z))), z = koopman^T
// Persistent tcgen05 SS-mode bf16 hi/lo-split GEMMs, TMEM double-buffered
// accumulators, deferred epilogue; s/t MLPs merged; diag fused into layer 3.
// ---------------------------------------------------------------------------

#if defined(__CUDA_ARCH__) && (__CUDA_ARCH__ >= 1000) && \
    (defined(__CUDA_ARCH_FEAT_SM103_ALL) || defined(__CUDA_ARCH_FEAT_SM100_ALL) || \
     defined(__CUDA_ARCH_SPECIFIC__))
#define TC_OK 1
#else
#define TC_OK 0
#endif

static constexpr int B_  = 2048;
static constexpr int R_  = B_ * 64;        // 131072 rows
static constexpr int NW  = 1024;           // combined width (s|t)
static constexpr int NTILES = (R_ / 128) * (NW / 256);   // 4096

static constexpr size_t SZ_Z   = (size_t)R_ * 64 * 2;
static constexpr size_t SZ_H   = (size_t)R_ * NW * 2;
static constexpr size_t SZ_DS  = (size_t)R_ * 4;
static constexpr size_t WT_ELEMS = (size_t)NW * 64 + (size_t)NW * 512 * 2;
static constexpr size_t SZ_WT  = WT_ELEMS * 2;
static constexpr size_t SZ_W4T = (size_t)2 * 64 * 512 * 4;

static constexpr size_t OFF_ZH   = 0;
static constexpr size_t OFF_ZL   = OFF_ZH  + SZ_Z;
static constexpr size_t OFF_H0H  = OFF_ZL  + SZ_Z;
static constexpr size_t OFF_H0L  = OFF_H0H + SZ_H;
static constexpr size_t OFF_H1H  = OFF_H0L + SZ_H;
static constexpr size_t OFF_H1L  = OFF_H1H + SZ_H;
static constexpr size_t OFF_DS   = OFF_H1L + SZ_H;
static constexpr size_t OFF_DT   = OFF_DS  + SZ_DS;
static constexpr size_t OFF_WTH  = OFF_DT  + SZ_DS;
static constexpr size_t OFF_WTL  = OFF_WTH + SZ_WT;
static constexpr size_t OFF_W4T  = OFF_WTL + SZ_WT;
static constexpr size_t SCRATCH_BYTES = OFF_W4T + SZ_W4T;

__device__ __align__(256) unsigned char g_scratch[SCRATCH_BYTES];

static constexpr size_t WOFF_1 = 0;
static constexpr size_t WOFF_2 = (size_t)NW * 64;
static constexpr size_t WOFF_3 = WOFF_2 + (size_t)NW * 512;

// ---------------------------------------------------------------------------
// common helpers
// ---------------------------------------------------------------------------
__device__ __forceinline__ void cp16(uint32_t s, const void* g) {
    asm volatile("cp.async.cg.shared.global [%0], [%1], 16;\n" :: "r"(s), "l"(g));
}
__device__ __forceinline__ void cp_commit() {
    asm volatile("cp.async.commit_group;\n");
}
__device__ __forceinline__ void split2(float v, __nv_bfloat16& hi, __nv_bfloat16& lo) {
    hi = __float2bfloat16(v);
    lo = __float2bfloat16(v - __bfloat162float(hi));
}
__device__ __forceinline__ uint32_t smem_u32(const void* p) {
    return (uint32_t)__cvta_generic_to_shared(p);
}

#if TC_OK
__device__ __forceinline__ uint32_t elect_one_pred() {
    uint32_t pred;
    asm volatile(
        "{\n\t.reg .pred p;\n\t"
        "elect.sync _|p, 0xFFFFFFFF;\n\t"
        "selp.b32 %0, 1, 0, p;\n\t}"
        : "=r"(pred));
    return pred;
}
__device__ __forceinline__ void mbar_init(uint32_t mbar, uint32_t cnt) {
    asm volatile("mbarrier.init.shared.b64 [%0], %1;" :: "r"(mbar), "r"(cnt) : "memory");
}
__device__ __forceinline__ void mbar_inval(uint32_t mbar) {
    asm volatile("mbarrier.inval.shared.b64 [%0];" :: "r"(mbar) : "memory");
}
__device__ __forceinline__ void mbar_wait(uint32_t mbar, uint32_t parity) {
    asm volatile(
        "{\n\t.reg .pred P1;\n\t"
        "WAIT_LOOP_%=:\n\t"
        "mbarrier.try_wait.parity.acquire.cta.shared::cta.b64 P1, [%0], %1, 0x989680;\n\t"
        "@P1 bra.uni WAIT_DONE_%=;\n\t"
        "bra.uni WAIT_LOOP_%=;\n\t"
        "WAIT_DONE_%=:\n\t}"
        :: "r"(mbar), "r"(parity) : "memory");
}
__device__ __forceinline__ void tcgen05_commit(uint32_t mbar) {
    asm volatile(
        "tcgen05.commit.cta_group::1.mbarrier::arrive::one.shared::cluster.b64 [%0];"
        :: "r"(mbar) : "memory");
}
__device__ __forceinline__ void fence_proxy_async_cta() {
    asm volatile("fence.proxy.async.shared::cta;" ::: "memory");
}

static constexpr uint64_t SMEM_DESC_BASE_SW128 =
    (uint64_t(2)  << 61) | (uint64_t(1) << 46) | (uint64_t(64) << 32) | (uint64_t(1) << 16);
__device__ __forceinline__ uint64_t make_desc(uint32_t addr) {
    return SMEM_DESC_BASE_SW128 | ((uint64_t)(addr >> 4) & 0x3FFF);
}

// idesc: dtype F32, a/b BF16, N=256, M=128, cta_group::1
static constexpr uint32_t IDESC_F16 =
    (1u << 4) | (1u << 7) | (1u << 10) | ((256u / 8u) << 17) | ((128u / 16u) << 24);

__device__ __forceinline__ void mma_f16_ss(uint32_t d_tmem, uint64_t a_desc,
                                           uint64_t b_desc, uint32_t en) {
    asm volatile(
        "{\n\t.reg .pred p;\n\t"
        "setp.ne.u32 p, %4, 0;\n\t"
        "tcgen05.mma.cta_group::1.kind::f16 [%0], %1, %2, %3, {%5,%5,%5,%5}, p;\n\t}"
        :: "r"(d_tmem), "l"(a_desc), "l"(b_desc), "r"(IDESC_F16), "r"(en), "r"(0u)
        : "memory");
}

#define TC_ALLOC(dst_smem, n) \
    asm volatile("tcgen05.alloc.cta_group::1.sync.aligned.shared::cta.b32 [%0], %1;" \
                 :: "r"(dst_smem), "r"((uint32_t)(n)) : "memory")
#define TC_DEALLOC(tmem, n) \
    asm volatile("tcgen05.dealloc.cta_group::1.sync.aligned.b32 %0, %1;" \
                 :: "r"(tmem), "r"((uint32_t)(n)))
#define TC_FENCE_AFTER()  asm volatile("tcgen05.fence::after_thread_sync;" ::: "memory")
#define TC_FENCE_BEFORE() asm volatile("tcgen05.fence::before_thread_sync;" ::: "memory")
#define TC_WAIT_LD()      asm volatile("tcgen05.wait::ld.sync.aligned;" ::: "memory")

#define TC_LD_X32(r, addr) \
    asm volatile( \
        "tcgen05.ld.sync.aligned.32x32b.x32.b32 " \
        "{%0, %1, %2, %3, %4, %5, %6, %7, " \
        " %8, %9, %10, %11, %12, %13, %14, %15, " \
        " %16, %17, %18, %19, %20, %21, %22, %23, " \
        " %24, %25, %26, %27, %28, %29, %30, %31}, [%32];" \
        : "=r"((r)[0]),  "=r"((r)[1]),  "=r"((r)[2]),  "=r"((r)[3]), \
          "=r"((r)[4]),  "=r"((r)[5]),  "=r"((r)[6]),  "=r"((r)[7]), \
          "=r"((r)[8]),  "=r"((r)[9]),  "=r"((r)[10]), "=r"((r)[11]), \
          "=r"((r)[12]), "=r"((r)[13]), "=r"((r)[14]), "=r"((r)[15]), \
          "=r"((r)[16]), "=r"((r)[17]), "=r"((r)[18]), "=r"((r)[19]), \
          "=r"((r)[20]), "=r"((r)[21]), "=r"((r)[22]), "=r"((r)[23]), \
          "=r"((r)[24]), "=r"((r)[25]), "=r"((r)[26]), "=r"((r)[27]), \
          "=r"((r)[28]), "=r"((r)[29]), "=r"((r)[30]), "=r"((r)[31]) \
        : "r"(addr))
#endif  // TC_OK

__device__ __forceinline__ void mma16816(float c[4], const uint32_t a[4], const uint32_t b[2]) {
    asm volatile(
        "mma.sync.aligned.m16n8k16.row.col.f32.bf16.bf16.f32 "
        "{%0,%1,%2,%3}, {%4,%5,%6,%7}, {%8,%9}, {%0,%1,%2,%3};\n"
        : "+f"(c[0]), "+f"(c[1]), "+f"(c[2]), "+f"(c[3])
        : "r"(a[0]), "r"(a[1]), "r"(a[2]), "r"(a[3]), "r"(b[0]), "r"(b[1]));
}

// ---------------------------------------------------------------------------
// prep kernels
// ---------------------------------------------------------------------------
__global__ void split_z_kernel(const float* __restrict__ koop) {
    __nv_bfloat16* Zh = (__nv_bfloat16*)(g_scratch + OFF_ZH);
    __nv_bfloat16* Zl = (__nv_bfloat16*)(g_scratch + OFF_ZL);
    __shared__ float s[64][65];
    int b = blockIdx.x;
    const float* src = koop + (size_t)b * 4096;
    for (int t = threadIdx.x; t < 4096; t += 256) {
        int l = t >> 6, i = t & 63;
        s[l][i] = src[t];
    }
    __syncthreads();
    for (int t = threadIdx.x; t < 4096; t += 256) {
        int i = t >> 6, l = t & 63;
        float v = s[l][i];
        __nv_bfloat16 h, lo; split2(v, h, lo);
        size_t o = (size_t)(b * 64 + i) * 64 + l;
        Zh[o] = h; Zl[o] = lo;
    }
}

__global__ void split_weight(const float* __restrict__ W, size_t elemOff, int fi) {
    __nv_bfloat16* Wth = (__nv_bfloat16*)(g_scratch + OFF_WTH) + elemOff;
    __nv_bfloat16* Wtl = (__nv_bfloat16*)(g_scratch + OFF_WTL) + elemOff;
    int idx = blockIdx.x * blockDim.x + threadIdx.x;
    if (idx >= fi * 512) return;
    int n = idx / fi, k = idx - n * fi;
    float v = W[(size_t)k * 512 + n];
    __nv_bfloat16 h, lo; split2(v, h, lo);
    Wth[idx] = h; Wtl[idx] = lo;
}

__global__ void transpose_w4(const float* __restrict__ W4, int sel) {
    float* W4t = (float*)(g_scratch + OFF_W4T) + (size_t)sel * 32768;
    int idx = blockIdx.x * blockDim.x + threadIdx.x;
    if (idx >= 64 * 512) return;
    int d = idx >> 9, k = idx & 511;
    W4t[idx] = W4[(size_t)k * 64 + d];
}

// ---------------------------------------------------------------------------
// persistent GEMM: per tile C = split(tanh(A @ Bt^T + bias)) or diag dots
// ---------------------------------------------------------------------------
static constexpr uint32_t STG_A_H = 0;
static constexpr uint32_t STG_A_L = 16384;
static constexpr uint32_t STG_B_H = 32768;
static constexpr uint32_t STG_B_L = 65536;
static constexpr uint32_t STG_SZ  = 98304;
static constexpr int GEMM_SMEM = 2 * 98304 + 1024;   // 197632 dynamic

#if TC_OK
__device__ __forceinline__ void load_stage(uint32_t tile, int st, int k0,
                                           int rowCTA, int colCTA, int K, int aLD, int aColOff,
                                           const __nv_bfloat16* Ah, const __nv_bfloat16* Al,
                                           const __nv_bfloat16* Bh, const __nv_bfloat16* Bl) {
    const uint32_t base = tile + (uint32_t)st * STG_SZ;
    const int tid = threadIdx.x;
    #pragma unroll
    for (int j = 0; j < 4; ++j) {            // A: 128 rows x 128B (SW128)
        int idx = tid + 256 * j;
        int row = idx >> 3, c16 = idx & 7;
        uint32_t boff = (uint32_t)(row * 128 + c16 * 16);
        uint32_t sw = boff ^ ((boff >> 3) & 0x70);
        const size_t g = (size_t)(rowCTA + row) * aLD + aColOff + k0 + c16 * 8;
        cp16(base + STG_A_H + sw, Ah + g);
        cp16(base + STG_A_L + sw, Al + g);
    }
    #pragma unroll
    for (int j = 0; j < 8; ++j) {            // B: 256 rows x 128B (SW128)
        int idx = tid + 256 * j;
        int row = idx >> 3, c16 = idx & 7;
        uint32_t boff = (uint32_t)(row * 128 + c16 * 16);
        uint32_t sw = boff ^ ((boff >> 3) & 0x70);
        const size_t g = (size_t)(colCTA + row) * K + k0 + c16 * 8;
        cp16(base + STG_B_H + sw, Bh + g);
        cp16(base + STG_B_L + sw, Bl + g);
    }
}

// deferred epilogue of one finished tile (MMA completion already waited)
__device__ __forceinline__ void epilogue_tc(uint32_t Dbuf, const float* sb,
                                            int rowCTA, int colCTA, int diagMode,
                                            __nv_bfloat16* Ch, __nv_bfloat16* Cl,
                                            const float* W4T, float* dsbuf, float* dtbuf,
                                            int warp, int lane) {
    TC_FENCE_AFTER();
    const int sub = warp & 3;
    const int colbase = (warp >> 2) * 128;
    const int row = rowCTA + sub * 32 + lane;

    if (!diagMode) {
        #pragma unroll
        for (int cc = 0; cc < 4; ++cc) {
            const int c0 = colbase + cc * 32;
            uint32_t r[32];
            TC_LD_X32(r, Dbuf + (uint32_t)c0);
            TC_WAIT_LD();
            uint32_t ph[16], pl[16];
            #pragma unroll
            for (int c = 0; c < 32; c += 2) {
                float v0 = tanhf(__uint_as_float(r[c])     + sb[c0 + c]);
                float v1 = tanhf(__uint_as_float(r[c + 1]) + sb[c0 + c + 1]);
                __nv_bfloat16 h0, l0, h1, l1;
                split2(v0, h0, l0); split2(v1, h1, l1);
                __nv_bfloat162 th = __halves2bfloat162(h0, h1);
                __nv_bfloat162 tl = __halves2bfloat162(l0, l1);
                ph[c >> 1] = *reinterpret_cast<uint32_t*>(&th);
                pl[c >> 1] = *reinterpret_cast<uint32_t*>(&tl);
            }
            const size_t o = (size_t)row * NW + colCTA + c0;
            uint4* dh = reinterpret_cast<uint4*>(Ch + o);
            uint4* dl = reinterpret_cast<uint4*>(Cl + o);
            #pragma unroll
            for (int q = 0; q < 4; ++q) {
                dh[q] = make_uint4(ph[4 * q], ph[4 * q + 1], ph[4 * q + 2], ph[4 * q + 3]);
                dl[q] = make_uint4(pl[4 * q], pl[4 * q + 1], pl[4 * q + 2], pl[4 * q + 3]);
            }
        }
    } else {
        const int sel = (colCTA >= 512);
        const float* w4 = W4T + (size_t)sel * 32768 + (size_t)(row & 63) * 512
                        + (colCTA - sel * 512) + colbase;
        float p = 0.f;
        #pragma unroll
        for (int cc = 0; cc < 4; ++cc) {
            const int c0 = colbase + cc * 32;
            uint32_t r[32];
            TC_LD_X32(r, Dbuf + (uint32_t)c0);
            TC_WAIT_LD();
            #pragma unroll
            for (int c = 0; c < 32; ++c) {
                float v = tanhf(__uint_as_float(r[c]) + sb[c0 + c]);
                p += v * w4[cc * 32 + c];
            }
        }
        atomicAdd((sel ? dtbuf : dsbuf) + row, p);
    }
    TC_FENCE_BEFORE();
}
#else
__device__ __forceinline__ void load_tiles_fb(__nv_bfloat16* smem, int st, int k0,
                                              int rowCTA, int colCTA, int K, int aLD, int aColOff,
                                              const __nv_bfloat16* Ah, const __nv_bfloat16* Al,
                                              const __nv_bfloat16* Bth, const __nv_bfloat16* Btl) {
    uint32_t sbase = smem_u32(smem);
    #pragma unroll
    for (int it = 0; it < 2; ++it) {
        int idx = it * 256 + threadIdx.x;
        int row = idx >> 2;
        int sc  = (idx & 3) * 8;
        uint32_t o = sbase + (uint32_t)st * (128 * 40 * 2)
                           + (uint32_t)row * (40 * 2) + (uint32_t)sc * 2;
        const size_t ga = (size_t)(rowCTA + row) * aLD + aColOff + k0 + sc;
        const size_t gb = (size_t)(colCTA + row) * K + k0 + sc;
        cp16(o,          Ah  + ga);
        cp16(o + 20480u, Al  + ga);
        cp16(o + 40960u, Bth + gb);
        cp16(o + 61440u, Btl + gb);
    }
}
#endif

__global__ void __launch_bounds__(256, 1)
gemm_p(size_t offAh, size_t offAl, int aLD, int splitA, size_t wElemOff,
       const float* __restrict__ bias_s, const float* __restrict__ bias_t,
       size_t offCh, size_t offCl, int K, int diagMode) {
    const __nv_bfloat16* Ah  = (const __nv_bfloat16*)(g_scratch + offAh);
    const __nv_bfloat16* Al  = (const __nv_bfloat16*)(g_scratch + offAl);
    const __nv_bfloat16* Bth = (const __nv_bfloat16*)(g_scratch + OFF_WTH) + wElemOff;
    const __nv_bfloat16* Btl = (const __nv_bfloat16*)(g_scratch + OFF_WTL) + wElemOff;
    __nv_bfloat16* Ch = (__nv_bfloat16*)(g_scratch + offCh);
    __nv_bfloat16* Cl = (__nv_bfloat16*)(g_scratch + offCl);
    const float* W4T = (const float*)(g_scratch + OFF_W4T);
    float* dsbuf = (float*)(g_scratch + OFF_DS);
    float* dtbuf = (float*)(g_scratch + OFF_DT);

#if TC_OK
    // =======================  persistent tcgen05 path  =======================
    extern __shared__ __align__(16) unsigned char dyn[];
    __shared__ __align__(16) uint32_t s_ctrl[4];     // [0] = tmem base
    __shared__ __align__(16) uint64_t s_mbars[2];    // per-stage-slot commit mbars
    __shared__ float sbias[2][256];

    const int tid  = threadIdx.x;
    const int warp = tid >> 5, lane = tid & 31;
    const int G = gridDim.x;

    const uint32_t tile = (smem_u32(dyn) + 1023u) & ~1023u;
    const uint32_t ctrl = smem_u32(s_ctrl);
    const uint32_t mbar0 = smem_u32(&s_mbars[0]);

    if (warp == 0) TC_ALLOC(ctrl, 512);
    if (tid == 0) { mbar_init(mbar0, 1); mbar_init(mbar0 + 8, 1); }
    __syncthreads();
    const uint32_t tmem = s_ctrl[0];

    const int nk = K >> 6;
    long c = 0;                 // global chunk counter for this CTA
    int lt = 0;                 // local tile counter (D-buffer parity)
    int prevRow = -1, prevCol = -1;
    bool havePrev = false;

    for (int t = blockIdx.x; t < NTILES; t += G, ++lt) {
        const int colCTA = (t & 3) * 256;
        const int rowCTA = (t >> 2) * 128;
        const int aColOff = splitA ? (colCTA & 512) : 0;
        {
            int cc = colCTA + tid;
            sbias[lt & 1][tid] = (cc < 512) ? bias_s[cc] : bias_t[cc - 512];
        }
        const uint32_t Dbuf = tmem + (uint32_t)((lt & 1) * 256);
        const int epiAt = (nk > 1) ? 1 : 0;

        for (int i = 0; i < nk; ++i, ++c) {
            const int slot = (int)(c & 1);
            if (c >= 2) {
                // stage slot free when commit of chunk c-2 done
                mbar_wait(mbar0 + 8 * slot, (uint32_t)(((c >> 1) + 1) & 1));
            }
            load_stage(tile, slot, i * 64, rowCTA, colCTA, K, aLD, aColOff, Ah, Al, Bth, Btl);
            cp_commit();

            if (i == epiAt && havePrev) {
                if (nk == 1) {
                    // need prev tile's (only) commit: chunk c-1
                    long pc = c - 1;
                    mbar_wait(mbar0 + 8 * (int)(pc & 1), (uint32_t)((pc >> 1) & 1));
                }
                // for nk>1 at i==1: the slot-wait above (commit c-2) IS the prev
                // tile's last commit — MMA of prev tile fully done.
                epilogue_tc(tmem + (uint32_t)(((lt - 1) & 1) * 256), sbias[(lt - 1) & 1],
                            prevRow, prevCol, diagMode, Ch, Cl, W4T, dsbuf, dtbuf, warp, lane);
            }

            asm volatile("cp.async.wait_group 0;\n" ::: "memory");
            fence_proxy_async_cta();
            __syncthreads();

            if (warp == 0 && elect_one_pred()) {
                const uint32_t sa = tile + (uint32_t)slot * STG_SZ;
                const uint64_t dAh = make_desc(sa + STG_A_H);
                const uint64_t dAl = make_desc(sa + STG_A_L);
                const uint64_t dBh = make_desc(sa + STG_B_H);
                const uint64_t dBl = make_desc(sa + STG_B_L);
                #pragma unroll
                for (int ks = 0; ks < 4; ++ks) {
                    const uint64_t ko = (uint64_t)(ks * 2);
                    mma_f16_ss(Dbuf, dAh + ko, dBh + ko, (i > 0 || ks > 0) ? 1u : 0u);
                    mma_f16_ss(Dbuf, dAh + ko, dBl + ko, 1u);
                    mma_f16_ss(Dbuf, dAl + ko, dBh + ko, 1u);
                }
                tcgen05_commit(mbar0 + 8 * slot);
            }
        }
        prevRow = rowCTA; prevCol = colCTA; havePrev = true;
    }

    // drain last tile
    if (havePrev) {
        long pc = c - 1;
        mbar_wait(mbar0 + 8 * (int)(pc & 1), (uint32_t)((pc >> 1) & 1));
        epilogue_tc(tmem + (uint32_t)(((lt - 1) & 1) * 256), sbias[(lt - 1) & 1],
                    prevRow, prevCol, diagMode, Ch, Cl, W4T, dsbuf, dtbuf, warp, lane);
    }

    __syncthreads();
    if (tid == 0) { mbar_inval(mbar0); mbar_inval(mbar0 + 8); }
    __syncthreads();
    if (warp == 0) TC_DEALLOC(tmem, 512);

#else
    // ============ mma.sync fallback (grid-stride persistent) ============
    extern __shared__ __align__(16) __nv_bfloat16 smem[];
    const int tid  = threadIdx.x;
    const int warp = tid >> 5, lane = tid & 31;
    const int wm = warp & 1, wn = warp >> 1;
    const int g  = lane >> 2, tg = lane & 3;

    for (int t = blockIdx.x; t < NTILES; t += gridDim.x) {
        const int colBase256 = (t & 3) * 256;
        const int rowCTA = (t >> 2) * 128;
        const int aColOff = splitA ? (colBase256 & 512) : 0;

        for (int nh = 0; nh < 2; ++nh) {
            const int colCTA = colBase256 + nh * 128;

            float acc[4][4][4];
            #pragma unroll
            for (int a = 0; a < 4; ++a)
                #pragma unroll
                for (int b = 0; b < 4; ++b)
                    #pragma unroll
                    for (int cc2 = 0; cc2 < 4; ++cc2) acc[a][b][cc2] = 0.f;

            const int nk = K / 32;
            __syncthreads();
            load_tiles_fb(smem, 0, 0, rowCTA, colCTA, K, aLD, aColOff, Ah, Al, Bth, Btl);
            cp_commit();

            for (int kk = 0; kk < nk; ++kk) {
                if (kk + 1 < nk) {
                    load_tiles_fb(smem, (kk + 1) & 1, (kk + 1) * 32, rowCTA, colCTA, K, aLD,
                                  aColOff, Ah, Al, Bth, Btl);
                    cp_commit();
                    asm volatile("cp.async.wait_group 1;\n");
                } else {
                    asm volatile("cp.async.wait_group 0;\n");
                }
                __syncthreads();

                const int st = kk & 1;
                const __nv_bfloat16* pAh = smem + (size_t)st * 128 * 40;
                const __nv_bfloat16* pAl = pAh + 2 * 128 * 40;
                const __nv_bfloat16* pBh = pAh + 4 * 128 * 40;
                const __nv_bfloat16* pBl = pAh + 6 * 128 * 40;

                #pragma unroll
                for (int kh = 0; kh < 2; ++kh) {
                    const int k16 = kh * 16 + 2 * tg;
                    uint32_t afh[4][4], afl[4][4];
                    #pragma unroll
                    for (int mt = 0; mt < 4; ++mt) {
                        const int r0 = (wm * 64 + mt * 16 + g) * 40 + k16;
                        const __nv_bfloat16* p = pAh + r0;
                        const __nv_bfloat16* q = pAl + r0;
                        afh[mt][0] = *(const uint32_t*)(p);
                        afh[mt][1] = *(const uint32_t*)(p + 8 * 40);
                        afh[mt][2] = *(const uint32_t*)(p + 8);
                        afh[mt][3] = *(const uint32_t*)(p + 8 * 40 + 8);
                        afl[mt][0] = *(const uint32_t*)(q);
                        afl[mt][1] = *(const uint32_t*)(q + 8 * 40);
                        afl[mt][2] = *(const uint32_t*)(q + 8);
                        afl[mt][3] = *(const uint32_t*)(q + 8 * 40 + 8);
                    }
                    #pragma unroll
                    for (int nt = 0; nt < 4; ++nt) {
                        const int c0 = (wn * 32 + nt * 8 + g) * 40 + k16;
                        const __nv_bfloat16* pb = pBh + c0;
                        const __nv_bfloat16* qb = pBl + c0;
                        uint32_t bh[2] = { *(const uint32_t*)(pb), *(const uint32_t*)(pb + 8) };
                        uint32_t bl[2] = { *(const uint32_t*)(qb), *(const uint32_t*)(qb + 8) };
                        #pragma unroll
                        for (int mt = 0; mt < 4; ++mt) {
                            mma16816(acc[mt][nt], afh[mt], bh);
                            mma16816(acc[mt][nt], afh[mt], bl);
                            mma16816(acc[mt][nt], afl[mt], bh);
                        }
                    }
                }
                __syncthreads();
            }

            #pragma unroll
            for (int mt = 0; mt < 4; ++mt) {
                const int r0 = rowCTA + wm * 64 + mt * 16 + g;
                #pragma unroll
                for (int nt = 0; nt < 4; ++nt) {
                    const int cc = colCTA + wn * 32 + nt * 8 + 2 * tg;
                    const float bb0 = (cc < 512) ? bias_s[cc] : bias_t[cc - 512];
                    const float bb1 = (cc + 1 < 512) ? bias_s[cc + 1] : bias_t[cc + 1 - 512];
                    #pragma unroll
                    for (int h = 0; h < 2; ++h) {
                        const int r = r0 + h * 8;
                        float v0 = tanhf(acc[mt][nt][2 * h + 0] + bb0);
                        float v1 = tanhf(acc[mt][nt][2 * h + 1] + bb1);
                        if (!diagMode) {
                            __nv_bfloat16 h0, l0, h1, l1;
                            split2(v0, h0, l0); split2(v1, h1, l1);
                            size_t off = (size_t)r * NW + cc;
                            *reinterpret_cast<__nv_bfloat162*>(Ch + off) = __halves2bfloat162(h0, h1);
                            *reinterpret_cast<__nv_bfloat162*>(Cl + off) = __halves2bfloat162(l0, l1);
                        } else {
                            const int sel = (cc >= 512);
                            const float* w4 = W4T + (size_t)sel * 32768 + (size_t)(r & 63) * 512
                                            + (cc - sel * 512);
                            atomicAdd((sel ? dtbuf : dsbuf) + r, v0 * w4[0] + v1 * w4[1]);
                        }
                    }
                }
            }
        }
    }
#endif
}

// out = (x - (dt + b4_t[r%64])) * exp(-(ds + b4_s[r%64]))
__global__ void final_combine2(const float* __restrict__ x,
                               const float* __restrict__ b4s,
                               const float* __restrict__ b4t,
                               float* __restrict__ out) {
    const float* ds = (const float*)(g_scratch + OFF_DS);
    const float* dt = (const float*)(g_scratch + OFF_DT);
    int r = blockIdx.x * blockDim.x + threadIdx.x;
    if (r < R_) {
        int i = r & 63;
        out[r] = (x[r] - (dt[r] + b4t[i])) * expf(-(ds[r] + b4s[i]));
    }
}

// ---------------------------------------------------------------------------
// launch
// ---------------------------------------------------------------------------
extern "C" void kernel_launch(void* const* d_in, const int* in_sizes, int n_in,
                              void* d_out, int out_size) {
    (void)in_sizes; (void)n_in; (void)out_size;
    const float* x    = (const float*)d_in[0];
    const float* koop = (const float*)d_in[1];
    const float* W1[2] = { (const float*)d_in[2],  (const float*)d_in[10] };
    const float* b1[2] = { (const float*)d_in[3],  (const float*)d_in[11] };
    const float* W2[2] = { (const float*)d_in[4],  (const float*)d_in[12] };
    const float* b2[2] = { (const float*)d_in[5],  (const float*)d_in[13] };
    const float* W3[2] = { (const float*)d_in[6],  (const float*)d_in[14] };
    const float* b3[2] = { (const float*)d_in[7],  (const float*)d_in[15] };
    const float* W4[2] = { (const float*)d_in[8],  (const float*)d_in[16] };
    const float* b4[2] = { (const float*)d_in[9],  (const float*)d_in[17] };
    float* out = (float*)d_out;

    cudaFuncSetAttribute((const void*)gemm_p,
                         cudaFuncAttributeMaxDynamicSharedMemorySize, GEMM_SMEM);

    int nsm = 0;
    cudaDeviceGetAttribute(&nsm, cudaDevAttrMultiProcessorCount, 0);
    if (nsm <= 0) nsm = 148;

    // prep
    split_z_kernel<<<B_, 256>>>(koop);
    for (int m = 0; m < 2; ++m) {
        split_weight<<<(512 * 64  + 255) / 256, 256>>>(W1[m], WOFF_1 + (size_t)m * 512 * 64,  64);
        split_weight<<<(512 * 512 + 255) / 256, 256>>>(W2[m], WOFF_2 + (size_t)m * 512 * 512, 512);
        split_weight<<<(512 * 512 + 255) / 256, 256>>>(W3[m], WOFF_3 + (size_t)m * 512 * 512, 512);
        transpose_w4<<<(64 * 512 + 255) / 256, 256>>>(W4[m], m);
    }

    // zero ds/dt accumulators
    void* base = nullptr;
    cudaGetSymbolAddress(&base, g_scratch);
    cudaMemsetAsync((unsigned char*)base + OFF_DS, 0, 2 * SZ_DS, 0);

    // layer 1: Z (K=64) -> H0
    gemm_p<<<nsm, 256, GEMM_SMEM>>>(OFF_ZH, OFF_ZL, 64, 0, WOFF_1,
                                    b1[0], b1[1], OFF_H0H, OFF_H0L, 64, 0);
    // layer 2: H0 -> H1 (block-diagonal via aColOff)
    gemm_p<<<nsm, 256, GEMM_SMEM>>>(OFF_H0H, OFF_H0L, NW, 1, WOFF_2,
                                    b2[0], b2[1], OFF_H1H, OFF_H1L, 512, 0);
    // layer 3: H1 -> diag dots into ds/dt (no C store)
    gemm_p<<<nsm, 256, GEMM_SMEM>>>(OFF_H1H, OFF_H1L, NW, 1, WOFF_3,
                                    b3[0], b3[1], OFF_H0H, OFF_H0L, 512, 1);

    final_combine2<<<R_ / 256, 256>>>(x, b4[0], b4[1], out);
}

// round 13
// speedup vs baseline: 1.8366x; 1.8366x over previous
#include <cuda_runtime.h>
#include <cuda_bf16.h>
#include <cstdint>
#include <cstddef>

// ---------------------------------------------------------------------------
// Decoder: out = (x - diag(t_mlp(z))) * exp(-diag(s_mlp(z))), z = koopman^T
// Persistent tcgen05 SS-mode bf16 hi/lo-split GEMMs, software-pipelined
// cp.async double buffer, TMEM ping-pong accumulators, deferred epilogue
// overlapped with MMA; s/t MLPs merged; diag fused into layer 3.
// ---------------------------------------------------------------------------

#if defined(__CUDA_ARCH__) && (__CUDA_ARCH__ >= 1000) && \
    (defined(__CUDA_ARCH_FEAT_SM103_ALL) || defined(__CUDA_ARCH_FEAT_SM100_ALL) || \
     defined(__CUDA_ARCH_SPECIFIC__))
#define TC_OK 1
#else
#define TC_OK 0
#endif

static constexpr int B_  = 2048;
static constexpr int R_  = B_ * 64;        // 131072 rows
static constexpr int NW  = 1024;           // combined width (s|t)
static constexpr int NTILES = (R_ / 128) * (NW / 256);   // 4096

static constexpr size_t SZ_Z   = (size_t)R_ * 64 * 2;
static constexpr size_t SZ_H   = (size_t)R_ * NW * 2;
static constexpr size_t SZ_DS  = (size_t)R_ * 4;
static constexpr size_t WT_ELEMS = (size_t)NW * 64 + (size_t)NW * 512 * 2;
static constexpr size_t SZ_WT  = WT_ELEMS * 2;
static constexpr size_t SZ_W4T = (size_t)2 * 64 * 512 * 4;

static constexpr size_t OFF_ZH   = 0;
static constexpr size_t OFF_ZL   = OFF_ZH  + SZ_Z;
static constexpr size_t OFF_H0H  = OFF_ZL  + SZ_Z;
static constexpr size_t OFF_H0L  = OFF_H0H + SZ_H;
static constexpr size_t OFF_H1H  = OFF_H0L + SZ_H;
static constexpr size_t OFF_H1L  = OFF_H1H + SZ_H;
static constexpr size_t OFF_DS   = OFF_H1L + SZ_H;
static constexpr size_t OFF_DT   = OFF_DS  + SZ_DS;
static constexpr size_t OFF_WTH  = OFF_DT  + SZ_DS;
static constexpr size_t OFF_WTL  = OFF_WTH + SZ_WT;
static constexpr size_t OFF_W4T  = OFF_WTL + SZ_WT;
static constexpr size_t SCRATCH_BYTES = OFF_W4T + SZ_W4T;

__device__ __align__(256) unsigned char g_scratch[SCRATCH_BYTES];

static constexpr size_t WOFF_1 = 0;
static constexpr size_t WOFF_2 = (size_t)NW * 64;
static constexpr size_t WOFF_3 = WOFF_2 + (size_t)NW * 512;

// ---------------------------------------------------------------------------
// common helpers
// ---------------------------------------------------------------------------
__device__ __forceinline__ void cp16(uint32_t s, const void* g) {
    asm volatile("cp.async.cg.shared.global [%0], [%1], 16;\n" :: "r"(s), "l"(g));
}
__device__ __forceinline__ void cp_commit() {
    asm volatile("cp.async.commit_group;\n");
}
__device__ __forceinline__ void split2(float v, __nv_bfloat16& hi, __nv_bfloat16& lo) {
    hi = __float2bfloat16(v);
    lo = __float2bfloat16(v - __bfloat162float(hi));
}
__device__ __forceinline__ uint32_t smem_u32(const void* p) {
    return (uint32_t)__cvta_generic_to_shared(p);
}

#if TC_OK
__device__ __forceinline__ uint32_t elect_one_pred() {
    uint32_t pred;
    asm volatile(
        "{\n\t.reg .pred p;\n\t"
        "elect.sync _|p, 0xFFFFFFFF;\n\t"
        "selp.b32 %0, 1, 0, p;\n\t}"
        : "=r"(pred));
    return pred;
}
__device__ __forceinline__ void mbar_init(uint32_t mbar, uint32_t cnt) {
    asm volatile("mbarrier.init.shared.b64 [%0], %1;" :: "r"(mbar), "r"(cnt) : "memory");
}
__device__ __forceinline__ void mbar_inval(uint32_t mbar) {
    asm volatile("mbarrier.inval.shared.b64 [%0];" :: "r"(mbar) : "memory");
}
__device__ __forceinline__ void mbar_wait(uint32_t mbar, uint32_t parity) {
    asm volatile(
        "{\n\t.reg .pred P1;\n\t"
        "WAIT_LOOP_%=:\n\t"
        "mbarrier.try_wait.parity.acquire.cta.shared::cta.b64 P1, [%0], %1, 0x989680;\n\t"
        "@P1 bra.uni WAIT_DONE_%=;\n\t"
        "bra.uni WAIT_LOOP_%=;\n\t"
        "WAIT_DONE_%=:\n\t}"
        :: "r"(mbar), "r"(parity) : "memory");
}
__device__ __forceinline__ void tcgen05_commit(uint32_t mbar) {
    asm volatile(
        "tcgen05.commit.cta_group::1.mbarrier::arrive::one.shared::cluster.b64 [%0];"
        :: "r"(mbar) : "memory");
}
__device__ __forceinline__ void fence_proxy_async_cta() {
    asm volatile("fence.proxy.async.shared::cta;" ::: "memory");
}

static constexpr uint64_t SMEM_DESC_BASE_SW128 =
    (uint64_t(2)  << 61) | (uint64_t(1) << 46) | (uint64_t(64) << 32) | (uint64_t(1) << 16);
__device__ __forceinline__ uint64_t make_desc(uint32_t addr) {
    return SMEM_DESC_BASE_SW128 | ((uint64_t)(addr >> 4) & 0x3FFF);
}

// idesc: dtype F32, a/b BF16, N=256, M=128, cta_group::1
static constexpr uint32_t IDESC_F16 =
    (1u << 4) | (1u << 7) | (1u << 10) | ((256u / 8u) << 17) | ((128u / 16u) << 24);

__device__ __forceinline__ void mma_f16_ss(uint32_t d_tmem, uint64_t a_desc,
                                           uint64_t b_desc, uint32_t en) {
    asm volatile(
        "{\n\t.reg .pred p;\n\t"
        "setp.ne.u32 p, %4, 0;\n\t"
        "tcgen05.mma.cta_group::1.kind::f16 [%0], %1, %2, %3, {%5,%5,%5,%5}, p;\n\t}"
        :: "r"(d_tmem), "l"(a_desc), "l"(b_desc), "r"(IDESC_F16), "r"(en), "r"(0u)
        : "memory");
}

#define TC_ALLOC(dst_smem, n) \
    asm volatile("tcgen05.alloc.cta_group::1.sync.aligned.shared::cta.b32 [%0], %1;" \
                 :: "r"(dst_smem), "r"((uint32_t)(n)) : "memory")
#define TC_DEALLOC(tmem, n) \
    asm volatile("tcgen05.dealloc.cta_group::1.sync.aligned.b32 %0, %1;" \
                 :: "r"(tmem), "r"((uint32_t)(n)))
#define TC_FENCE_AFTER()  asm volatile("tcgen05.fence::after_thread_sync;" ::: "memory")
#define TC_FENCE_BEFORE() asm volatile("tcgen05.fence::before_thread_sync;" ::: "memory")
#define TC_WAIT_LD()      asm volatile("tcgen05.wait::ld.sync.aligned;" ::: "memory")

#define TC_LD_X32(r, addr) \
    asm volatile( \
        "tcgen05.ld.sync.aligned.32x32b.x32.b32 " \
        "{%0, %1, %2, %3, %4, %5, %6, %7, " \
        " %8, %9, %10, %11, %12, %13, %14, %15, " \
        " %16, %17, %18, %19, %20, %21, %22, %23, " \
        " %24, %25, %26, %27, %28, %29, %30, %31}, [%32];" \
        : "=r"((r)[0]),  "=r"((r)[1]),  "=r"((r)[2]),  "=r"((r)[3]), \
          "=r"((r)[4]),  "=r"((r)[5]),  "=r"((r)[6]),  "=r"((r)[7]), \
          "=r"((r)[8]),  "=r"((r)[9]),  "=r"((r)[10]), "=r"((r)[11]), \
          "=r"((r)[12]), "=r"((r)[13]), "=r"((r)[14]), "=r"((r)[15]), \
          "=r"((r)[16]), "=r"((r)[17]), "=r"((r)[18]), "=r"((r)[19]), \
          "=r"((r)[20]), "=r"((r)[21]), "=r"((r)[22]), "=r"((r)[23]), \
          "=r"((r)[24]), "=r"((r)[25]), "=r"((r)[26]), "=r"((r)[27]), \
          "=r"((r)[28]), "=r"((r)[29]), "=r"((r)[30]), "=r"((r)[31]) \
        : "r"(addr))
#endif  // TC_OK

__device__ __forceinline__ void mma16816(float c[4], const uint32_t a[4], const uint32_t b[2]) {
    asm volatile(
        "mma.sync.aligned.m16n8k16.row.col.f32.bf16.bf16.f32 "
        "{%0,%1,%2,%3}, {%4,%5,%6,%7}, {%8,%9}, {%0,%1,%2,%3};\n"
        : "+f"(c[0]), "+f"(c[1]), "+f"(c[2]), "+f"(c[3])
        : "r"(a[0]), "r"(a[1]), "r"(a[2]), "r"(a[3]), "r"(b[0]), "r"(b[1]));
}

// ---------------------------------------------------------------------------
// prep kernels
// ---------------------------------------------------------------------------
__global__ void split_z_kernel(const float* __restrict__ koop) {
    __nv_bfloat16* Zh = (__nv_bfloat16*)(g_scratch + OFF_ZH);
    __nv_bfloat16* Zl = (__nv_bfloat16*)(g_scratch + OFF_ZL);
    __shared__ float s[64][65];
    int b = blockIdx.x;
    const float* src = koop + (size_t)b * 4096;
    for (int t = threadIdx.x; t < 4096; t += 256) {
        int l = t >> 6, i = t & 63;
        s[l][i] = src[t];
    }
    __syncthreads();
    for (int t = threadIdx.x; t < 4096; t += 256) {
        int i = t >> 6, l = t & 63;
        float v = s[l][i];
        __nv_bfloat16 h, lo; split2(v, h, lo);
        size_t o = (size_t)(b * 64 + i) * 64 + l;
        Zh[o] = h; Zl[o] = lo;
    }
}

__global__ void split_weight(const float* __restrict__ W, size_t elemOff, int fi) {
    __nv_bfloat16* Wth = (__nv_bfloat16*)(g_scratch + OFF_WTH) + elemOff;
    __nv_bfloat16* Wtl = (__nv_bfloat16*)(g_scratch + OFF_WTL) + elemOff;
    int idx = blockIdx.x * blockDim.x + threadIdx.x;
    if (idx >= fi * 512) return;
    int n = idx / fi, k = idx - n * fi;
    float v = W[(size_t)k * 512 + n];
    __nv_bfloat16 h, lo; split2(v, h, lo);
    Wth[idx] = h; Wtl[idx] = lo;
}

__global__ void transpose_w4(const float* __restrict__ W4, int sel) {
    float* W4t = (float*)(g_scratch + OFF_W4T) + (size_t)sel * 32768;
    int idx = blockIdx.x * blockDim.x + threadIdx.x;
    if (idx >= 64 * 512) return;
    int d = idx >> 9, k = idx & 511;
    W4t[idx] = W4[(size_t)k * 64 + d];
}

// ---------------------------------------------------------------------------
// persistent GEMM
// ---------------------------------------------------------------------------
static constexpr uint32_t STG_A_H = 0;
static constexpr uint32_t STG_A_L = 16384;
static constexpr uint32_t STG_B_H = 32768;
static constexpr uint32_t STG_B_L = 65536;
static constexpr uint32_t STG_SZ  = 98304;
static constexpr int GEMM_SMEM = 2 * 98304 + 1024;   // dynamic

#if TC_OK
__device__ __forceinline__ void load_stage(uint32_t tile, int st, int k0,
                                           int rowCTA, int colCTA, int K, int aLD, int aColOff,
                                           const __nv_bfloat16* Ah, const __nv_bfloat16* Al,
                                           const __nv_bfloat16* Bh, const __nv_bfloat16* Bl) {
    const uint32_t base = tile + (uint32_t)st * STG_SZ;
    const int tid = threadIdx.x;
    #pragma unroll
    for (int j = 0; j < 4; ++j) {            // A: 128 rows x 128B (SW128)
        int idx = tid + 256 * j;
        int row = idx >> 3, c16 = idx & 7;
        uint32_t boff = (uint32_t)(row * 128 + c16 * 16);
        uint32_t sw = boff ^ ((boff >> 3) & 0x70);
        const size_t g = (size_t)(rowCTA + row) * aLD + aColOff + k0 + c16 * 8;
        cp16(base + STG_A_H + sw, Ah + g);
        cp16(base + STG_A_L + sw, Al + g);
    }
    #pragma unroll
    for (int j = 0; j < 8; ++j) {            // B: 256 rows x 128B (SW128)
        int idx = tid + 256 * j;
        int row = idx >> 3, c16 = idx & 7;
        uint32_t boff = (uint32_t)(row * 128 + c16 * 16);
        uint32_t sw = boff ^ ((boff >> 3) & 0x70);
        const size_t g = (size_t)(colCTA + row) * K + k0 + c16 * 8;
        cp16(base + STG_B_H + sw, Bh + g);
        cp16(base + STG_B_L + sw, Bl + g);
    }
}

// deferred epilogue of one finished tile (MMA completion already waited)
__device__ __forceinline__ void epilogue_tc(uint32_t Dbuf, const float* sb,
                                            int rowCTA, int colCTA, int diagMode,
                                            __nv_bfloat16* Ch, __nv_bfloat16* Cl,
                                            const float* W4T, float* dsbuf, float* dtbuf,
                                            int warp, int lane) {
    TC_FENCE_AFTER();
    const int sub = warp & 3;
    const int colbase = (warp >> 2) * 128;
    const int row = rowCTA + sub * 32 + lane;

    if (!diagMode) {
        #pragma unroll
        for (int cc = 0; cc < 4; ++cc) {
            const int c0 = colbase + cc * 32;
            uint32_t r[32];
            TC_LD_X32(r, Dbuf + (uint32_t)c0);
            TC_WAIT_LD();
            uint32_t ph[16], pl[16];
            #pragma unroll
            for (int c = 0; c < 32; c += 2) {
                float v0 = tanhf(__uint_as_float(r[c])     + sb[c0 + c]);
                float v1 = tanhf(__uint_as_float(r[c + 1]) + sb[c0 + c + 1]);
                __nv_bfloat16 h0, l0, h1, l1;
                split2(v0, h0, l0); split2(v1, h1, l1);
                __nv_bfloat162 th = __halves2bfloat162(h0, h1);
                __nv_bfloat162 tl = __halves2bfloat162(l0, l1);
                ph[c >> 1] = *reinterpret_cast<uint32_t*>(&th);
                pl[c >> 1] = *reinterpret_cast<uint32_t*>(&tl);
            }
            const size_t o = (size_t)row * NW + colCTA + c0;
            uint4* dh = reinterpret_cast<uint4*>(Ch + o);
            uint4* dl = reinterpret_cast<uint4*>(Cl + o);
            #pragma unroll
            for (int q = 0; q < 4; ++q) {
                dh[q] = make_uint4(ph[4 * q], ph[4 * q + 1], ph[4 * q + 2], ph[4 * q + 3]);
                dl[q] = make_uint4(pl[4 * q], pl[4 * q + 1], pl[4 * q + 2], pl[4 * q + 3]);
            }
        }
    } else {
        const int sel = (colCTA >= 512);
        const float* w4 = W4T + (size_t)sel * 32768 + (size_t)(row & 63) * 512
                        + (colCTA - sel * 512) + colbase;
        float p = 0.f;
        #pragma unroll
        for (int cc = 0; cc < 4; ++cc) {
            const int c0 = colbase + cc * 32;
            uint32_t r[32];
            TC_LD_X32(r, Dbuf + (uint32_t)c0);
            TC_WAIT_LD();
            #pragma unroll
            for (int c = 0; c < 32; ++c) {
                float v = tanhf(__uint_as_float(r[c]) + sb[c0 + c]);
                p += v * w4[cc * 32 + c];
            }
        }
        atomicAdd((sel ? dtbuf : dsbuf) + row, p);
    }
    TC_FENCE_BEFORE();
}
#else
__device__ __forceinline__ void load_tiles_fb(__nv_bfloat16* smem, int st, int k0,
                                              int rowCTA, int colCTA, int K, int aLD, int aColOff,
                                              const __nv_bfloat16* Ah, const __nv_bfloat16* Al,
                                              const __nv_bfloat16* Bth, const __nv_bfloat16* Btl) {
    uint32_t sbase = smem_u32(smem);
    #pragma unroll
    for (int it = 0; it < 2; ++it) {
        int idx = it * 256 + threadIdx.x;
        int row = idx >> 2;
        int sc  = (idx & 3) * 8;
        uint32_t o = sbase + (uint32_t)st * (128 * 40 * 2)
                           + (uint32_t)row * (40 * 2) + (uint32_t)sc * 2;
        const size_t ga = (size_t)(rowCTA + row) * aLD + aColOff + k0 + sc;
        const size_t gb = (size_t)(colCTA + row) * K + k0 + sc;
        cp16(o,          Ah  + ga);
        cp16(o + 20480u, Al  + ga);
        cp16(o + 40960u, Bth + gb);
        cp16(o + 61440u, Btl + gb);
    }
}
#endif

__global__ void __launch_bounds__(256, 1)
gemm_p(size_t offAh, size_t offAl, int aLD, int splitA, size_t wElemOff,
       const float* __restrict__ bias_s, const float* __restrict__ bias_t,
       size_t offCh, size_t offCl, int K, int diagMode) {
    const __nv_bfloat16* Ah  = (const __nv_bfloat16*)(g_scratch + offAh);
    const __nv_bfloat16* Al  = (const __nv_bfloat16*)(g_scratch + offAl);
    const __nv_bfloat16* Bth = (const __nv_bfloat16*)(g_scratch + OFF_WTH) + wElemOff;
    const __nv_bfloat16* Btl = (const __nv_bfloat16*)(g_scratch + OFF_WTL) + wElemOff;
    __nv_bfloat16* Ch = (__nv_bfloat16*)(g_scratch + offCh);
    __nv_bfloat16* Cl = (__nv_bfloat16*)(g_scratch + offCl);
    const float* W4T = (const float*)(g_scratch + OFF_W4T);
    float* dsbuf = (float*)(g_scratch + OFF_DS);
    float* dtbuf = (float*)(g_scratch + OFF_DT);

#if TC_OK
    // =======================  persistent tcgen05 path  =======================
    extern __shared__ __align__(16) unsigned char dyn[];
    __shared__ __align__(16) uint32_t s_ctrl[4];     // [0] = tmem base
    __shared__ __align__(16) uint64_t s_mbars[2];    // per-stage-slot commit mbars
    __shared__ float sbias[2][256];

    const int tid  = threadIdx.x;
    const int warp = tid >> 5, lane = tid & 31;
    const int G = gridDim.x;

    const uint32_t tile = (smem_u32(dyn) + 1023u) & ~1023u;
    const uint32_t ctrl = smem_u32(s_ctrl);
    const uint32_t mbar0 = smem_u32(&s_mbars[0]);

    if (warp == 0) TC_ALLOC(ctrl, 512);
    if (tid == 0) { mbar_init(mbar0, 1); mbar_init(mbar0 + 8, 1); }
    __syncthreads();
    const uint32_t tmem = s_ctrl[0];

    const int nk = K >> 6;
    const int ntl = (blockIdx.x < NTILES) ? ((NTILES - 1 - blockIdx.x) / G + 1) : 0;
    const long total = (long)ntl * nk;

    // wait for commit of chunk j (j-th commit overall; slot j&1; phase j>>1)
    #define WAIT_COMMIT(j) mbar_wait(mbar0 + 8 * (int)((j) & 1), (uint32_t)(((j) >> 1) & 1))

    // prologue: load chunk 0
    if (ntl > 0) {
        int t0 = blockIdx.x;
        int col0 = (t0 & 3) * 256, row0 = (t0 >> 2) * 128;
        int ao0 = splitA ? (col0 & 512) : 0;
        load_stage(tile, 0, 0, row0, col0, K, aLD, ao0, Ah, Al, Bth, Btl);
        cp_commit();
    }

    long c = 0;
    int prevRow = 0, prevCol = 0;
    int t = blockIdx.x;
    for (int lt = 0; lt < ntl; ++lt, t += G) {
        const int colCTA = (t & 3) * 256;
        const int rowCTA = (t >> 2) * 128;
        const int aColOff = splitA ? (colCTA & 512) : 0;
        {
            int cc = colCTA + tid;
            sbias[lt & 1][tid] = (cc < 512) ? bias_s[cc] : bias_t[cc - 512];
        }
        const uint32_t Dbuf = tmem + (uint32_t)((lt & 1) * 256);

        for (int i = 0; i < nk; ++i, ++c) {
            const int slot = (int)(c & 1);
            if (c + 1 < total) {
                if (c >= 1) WAIT_COMMIT(c - 1);            // frees slot^1, orders MMA
                // prefetch chunk c+1
                int pi = i + 1, prow = rowCTA, pcol = colCTA, pao = aColOff;
                if (pi == nk) {
                    int pt = t + G;
                    pi = 0; pcol = (pt & 3) * 256; prow = (pt >> 2) * 128;
                    pao = splitA ? (pcol & 512) : 0;
                }
                load_stage(tile, slot ^ 1, pi * 64, prow, pcol, K, aLD, pao, Ah, Al, Bth, Btl);
                cp_commit();
                asm volatile("cp.async.wait_group 1;\n" ::: "memory");  // chunk c ready
            } else {
                asm volatile("cp.async.wait_group 0;\n" ::: "memory");
            }
            fence_proxy_async_cta();
            __syncthreads();

            if (warp == 0 && elect_one_pred()) {
                const uint32_t sa = tile + (uint32_t)slot * STG_SZ;
                const uint64_t dAh = make_desc(sa + STG_A_H);
                const uint64_t dAl = make_desc(sa + STG_A_L);
                const uint64_t dBh = make_desc(sa + STG_B_H);
                const uint64_t dBl = make_desc(sa + STG_B_L);
                #pragma unroll
                for (int ks = 0; ks < 4; ++ks) {
                    const uint64_t ko = (uint64_t)(ks * 2);
                    mma_f16_ss(Dbuf, dAh + ko, dBh + ko, (i > 0 || ks > 0) ? 1u : 0u);
                    mma_f16_ss(Dbuf, dAh + ko, dBl + ko, 1u);
                    mma_f16_ss(Dbuf, dAl + ko, dBh + ko, 1u);
                }
                tcgen05_commit(mbar0 + 8 * slot);
            }

            // deferred epilogue of previous tile, overlapped with MMA of chunk c
            if (i == 0 && lt > 0) {
                if (c + 1 >= total) WAIT_COMMIT(c - 1);    // not yet waited above
                epilogue_tc(tmem + (uint32_t)(((lt - 1) & 1) * 256), sbias[(lt - 1) & 1],
                            prevRow, prevCol, diagMode, Ch, Cl, W4T, dsbuf, dtbuf, warp, lane);
            }
        }
        prevRow = rowCTA; prevCol = colCTA;
    }

    // drain: last tile's epilogue
    if (ntl > 0) {
        WAIT_COMMIT(total - 1);
        epilogue_tc(tmem + (uint32_t)(((ntl - 1) & 1) * 256), sbias[(ntl - 1) & 1],
                    prevRow, prevCol, diagMode, Ch, Cl, W4T, dsbuf, dtbuf, warp, lane);
    }
    #undef WAIT_COMMIT

    __syncthreads();
    if (tid == 0) { mbar_inval(mbar0); mbar_inval(mbar0 + 8); }
    __syncthreads();
    if (warp == 0) TC_DEALLOC(tmem, 512);

#else
    // ============ mma.sync fallback (grid-stride persistent) ============
    extern __shared__ __align__(16) __nv_bfloat16 smem[];
    const int tid  = threadIdx.x;
    const int warp = tid >> 5, lane = tid & 31;
    const int wm = warp & 1, wn = warp >> 1;
    const int g  = lane >> 2, tg = lane & 3;

    for (int t = blockIdx.x; t < NTILES; t += gridDim.x) {
        const int colBase256 = (t & 3) * 256;
        const int rowCTA = (t >> 2) * 128;
        const int aColOff = splitA ? (colBase256 & 512) : 0;

        for (int nh = 0; nh < 2; ++nh) {
            const int colCTA = colBase256 + nh * 128;

            float acc[4][4][4];
            #pragma unroll
            for (int a = 0; a < 4; ++a)
                #pragma unroll
                for (int b = 0; b < 4; ++b)
                    #pragma unroll
                    for (int cc2 = 0; cc2 < 4; ++cc2) acc[a][b][cc2] = 0.f;

            const int nk = K / 32;
            __syncthreads();
            load_tiles_fb(smem, 0, 0, rowCTA, colCTA, K, aLD, aColOff, Ah, Al, Bth, Btl);
            cp_commit();

            for (int kk = 0; kk < nk; ++kk) {
                if (kk + 1 < nk) {
                    load_tiles_fb(smem, (kk + 1) & 1, (kk + 1) * 32, rowCTA, colCTA, K, aLD,
                                  aColOff, Ah, Al, Bth, Btl);
                    cp_commit();
                    asm volatile("cp.async.wait_group 1;\n");
                } else {
                    asm volatile("cp.async.wait_group 0;\n");
                }
                __syncthreads();

                const int st = kk & 1;
                const __nv_bfloat16* pAh = smem + (size_t)st * 128 * 40;
                const __nv_bfloat16* pAl = pAh + 2 * 128 * 40;
                const __nv_bfloat16* pBh = pAh + 4 * 128 * 40;
                const __nv_bfloat16* pBl = pAh + 6 * 128 * 40;

                #pragma unroll
                for (int kh = 0; kh < 2; ++kh) {
                    const int k16 = kh * 16 + 2 * tg;
                    uint32_t afh[4][4], afl[4][4];
                    #pragma unroll
                    for (int mt = 0; mt < 4; ++mt) {
                        const int r0 = (wm * 64 + mt * 16 + g) * 40 + k16;
                        const __nv_bfloat16* p = pAh + r0;
                        const __nv_bfloat16* q = pAl + r0;
                        afh[mt][0] = *(const uint32_t*)(p);
                        afh[mt][1] = *(const uint32_t*)(p + 8 * 40);
                        afh[mt][2] = *(const uint32_t*)(p + 8);
                        afh[mt][3] = *(const uint32_t*)(p + 8 * 40 + 8);
                        afl[mt][0] = *(const uint32_t*)(q);
                        afl[mt][1] = *(const uint32_t*)(q + 8 * 40);
                        afl[mt][2] = *(const uint32_t*)(q + 8);
                        afl[mt][3] = *(const uint32_t*)(q + 8 * 40 + 8);
                    }
                    #pragma unroll
                    for (int nt = 0; nt < 4; ++nt) {
                        const int c0 = (wn * 32 + nt * 8 + g) * 40 + k16;
                        const __nv_bfloat16* pb = pBh + c0;
                        const __nv_bfloat16* qb = pBl + c0;
                        uint32_t bh[2] = { *(const uint32_t*)(pb), *(const uint32_t*)(pb + 8) };
                        uint32_t bl[2] = { *(const uint32_t*)(qb), *(const uint32_t*)(qb + 8) };
                        #pragma unroll
                        for (int mt = 0; mt < 4; ++mt) {
                            mma16816(acc[mt][nt], afh[mt], bh);
                            mma16816(acc[mt][nt], afh[mt], bl);
                            mma16816(acc[mt][nt], afl[mt], bh);
                        }
                    }
                }
                __syncthreads();
            }

            #pragma unroll
            for (int mt = 0; mt < 4; ++mt) {
                const int r0 = rowCTA + wm * 64 + mt * 16 + g;
                #pragma unroll
                for (int nt = 0; nt < 4; ++nt) {
                    const int cc = colCTA + wn * 32 + nt * 8 + 2 * tg;
                    const float bb0 = (cc < 512) ? bias_s[cc] : bias_t[cc - 512];
                    const float bb1 = (cc + 1 < 512) ? bias_s[cc + 1] : bias_t[cc + 1 - 512];
                    #pragma unroll
                    for (int h = 0; h < 2; ++h) {
                        const int r = r0 + h * 8;
                        float v0 = tanhf(acc[mt][nt][2 * h + 0] + bb0);
                        float v1 = tanhf(acc[mt][nt][2 * h + 1] + bb1);
                        if (!diagMode) {
                            __nv_bfloat16 h0, l0, h1, l1;
                            split2(v0, h0, l0); split2(v1, h1, l1);
                            size_t off = (size_t)r * NW + cc;
                            *reinterpret_cast<__nv_bfloat162*>(Ch + off) = __halves2bfloat162(h0, h1);
                            *reinterpret_cast<__nv_bfloat162*>(Cl + off) = __halves2bfloat162(l0, l1);
                        } else {
                            const int sel = (cc >= 512);
                            const float* w4 = W4T + (size_t)sel * 32768 + (size_t)(r & 63) * 512
                                            + (cc - sel * 512);
                            atomicAdd((sel ? dtbuf : dsbuf) + r, v0 * w4[0] + v1 * w4[1]);
                        }
                    }
                }
            }
        }
    }
#endif
}

// out = (x - (dt + b4_t[r%64])) * exp(-(ds + b4_s[r%64]))
__global__ void final_combine2(const float* __restrict__ x,
                               const float* __restrict__ b4s,
                               const float* __restrict__ b4t,
                               float* __restrict__ out) {
    const float* ds = (const float*)(g_scratch + OFF_DS);
    const float* dt = (const float*)(g_scratch + OFF_DT);
    int r = blockIdx.x * blockDim.x + threadIdx.x;
    if (r < R_) {
        int i = r & 63;
        out[r] = (x[r] - (dt[r] + b4t[i])) * expf(-(ds[r] + b4s[i]));
    }
}

// ---------------------------------------------------------------------------
// launch
// ---------------------------------------------------------------------------
extern "C" void kernel_launch(void* const* d_in, const int* in_sizes, int n_in,
                              void* d_out, int out_size) {
    (void)in_sizes; (void)n_in; (void)out_size;
    const float* x    = (const float*)d_in[0];
    const float* koop = (const float*)d_in[1];
    const float* W1[2] = { (const float*)d_in[2],  (const float*)d_in[10] };
    const float* b1[2] = { (const float*)d_in[3],  (const float*)d_in[11] };
    const float* W2[2] = { (const float*)d_in[4],  (const float*)d_in[12] };
    const float* b2[2] = { (const float*)d_in[5],  (const float*)d_in[13] };
    const float* W3[2] = { (const float*)d_in[6],  (const float*)d_in[14] };
    const float* b3[2] = { (const float*)d_in[7],  (const float*)d_in[15] };
    const float* W4[2] = { (const float*)d_in[8],  (const float*)d_in[16] };
    const float* b4[2] = { (const float*)d_in[9],  (const float*)d_in[17] };
    float* out = (float*)d_out;

    cudaFuncSetAttribute((const void*)gemm_p,
                         cudaFuncAttributeMaxDynamicSharedMemorySize, GEMM_SMEM);

    int nsm = 0;
    cudaDeviceGetAttribute(&nsm, cudaDevAttrMultiProcessorCount, 0);
    if (nsm <= 0) nsm = 148;

    // prep
    split_z_kernel<<<B_, 256>>>(koop);
    for (int m = 0; m < 2; ++m) {
        split_weight<<<(512 * 64  + 255) / 256, 256>>>(W1[m], WOFF_1 + (size_t)m * 512 * 64,  64);
        split_weight<<<(512 * 512 + 255) / 256, 256>>>(W2[m], WOFF_2 + (size_t)m * 512 * 512, 512);
        split_weight<<<(512 * 512 + 255) / 256, 256>>>(W3[m], WOFF_3 + (size_t)m * 512 * 512, 512);
        transpose_w4<<<(64 * 512 + 255) / 256, 256>>>(W4[m], m);
    }

    // zero ds/dt accumulators
    void* base = nullptr;
    cudaGetSymbolAddress(&base, g_scratch);
    cudaMemsetAsync((unsigned char*)base + OFF_DS, 0, 2 * SZ_DS, 0);

    // layer 1: Z (K=64) -> H0
    gemm_p<<<nsm, 256, GEMM_SMEM>>>(OFF_ZH, OFF_ZL, 64, 0, WOFF_1,
                                    b1[0], b1[1], OFF_H0H, OFF_H0L, 64, 0);
    // layer 2: H0 -> H1 (block-diagonal via aColOff)
    gemm_p<<<nsm, 256, GEMM_SMEM>>>(OFF_H0H, OFF_H0L, NW, 1, WOFF_2,
                                    b2[0], b2[1], OFF_H1H, OFF_H1L, 512, 0);
    // layer 3: H1 -> diag dots into ds/dt (no C store)
    gemm_p<<<nsm, 256, GEMM_SMEM>>>(OFF_H1H, OFF_H1L, NW, 1, WOFF_3,
                                    b3[0], b3[1], OFF_H0H, OFF_H0L, 512, 1);

    final_combine2<<<R_ / 256, 256>>>(x, b4[0], b4[1], out);
}

// round 15
// speedup vs baseline: 1.8393x; 1.0014x over previous
#include <cuda_runtime.h>
#include <cuda_bf16.h>
#include <cstdint>
#include <cstddef>

// ---------------------------------------------------------------------------
// Decoder: out = (x - diag(t_mlp(z))) * exp(-diag(s_mlp(z))), z = koopman^T
// Persistent tcgen05 GEMMs, N=512 tiles (A read once from DRAM), K-chunk 32
// with hi/lo interleaved in SW128 rows; diag fused into layer 3.
// ---------------------------------------------------------------------------

#if defined(__CUDA_ARCH__) && (__CUDA_ARCH__ >= 1000) && \
    (defined(__CUDA_ARCH_FEAT_SM103_ALL) || defined(__CUDA_ARCH_FEAT_SM100_ALL) || \
     defined(__CUDA_ARCH_SPECIFIC__))
#define TC_OK 1
#else
#define TC_OK 0
#endif

static constexpr int B_  = 2048;
static constexpr int R_  = B_ * 64;        // 131072 rows
static constexpr int NW  = 1024;           // combined width (s|t)
static constexpr int NTILES = (R_ / 128) * (NW / 256);   // 4096 (fallback tiling)
static constexpr int NT2 = (R_ / 128) * (NW / 512);      // 2048 (tc tiling)

static constexpr size_t SZ_Z   = (size_t)R_ * 64 * 2;
static constexpr size_t SZ_H   = (size_t)R_ * NW * 2;
static constexpr size_t SZ_DS  = (size_t)R_ * 4;
static constexpr size_t WT_ELEMS = (size_t)NW * 64 + (size_t)NW * 512 * 2;
static constexpr size_t SZ_WT  = WT_ELEMS * 2;
static constexpr size_t SZ_W4T = (size_t)2 * 64 * 512 * 4;

static constexpr size_t OFF_ZH   = 0;
static constexpr size_t OFF_ZL   = OFF_ZH  + SZ_Z;
static constexpr size_t OFF_H0H  = OFF_ZL  + SZ_Z;
static constexpr size_t OFF_H0L  = OFF_H0H + SZ_H;
static constexpr size_t OFF_H1H  = OFF_H0L + SZ_H;
static constexpr size_t OFF_H1L  = OFF_H1H + SZ_H;
static constexpr size_t OFF_DS   = OFF_H1L + SZ_H;
static constexpr size_t OFF_DT   = OFF_DS  + SZ_DS;
static constexpr size_t OFF_WTH  = OFF_DT  + SZ_DS;
static constexpr size_t OFF_WTL  = OFF_WTH + SZ_WT;
static constexpr size_t OFF_W4T  = OFF_WTL + SZ_WT;
static constexpr size_t SCRATCH_BYTES = OFF_W4T + SZ_W4T;

__device__ __align__(256) unsigned char g_scratch[SCRATCH_BYTES];

static constexpr size_t WOFF_1 = 0;
static constexpr size_t WOFF_2 = (size_t)NW * 64;
static constexpr size_t WOFF_3 = WOFF_2 + (size_t)NW * 512;

// ---------------------------------------------------------------------------
// common helpers
// ---------------------------------------------------------------------------
__device__ __forceinline__ void cp16(uint32_t s, const void* g) {
    asm volatile("cp.async.cg.shared.global [%0], [%1], 16;\n" :: "r"(s), "l"(g));
}
__device__ __forceinline__ void cp_commit() {
    asm volatile("cp.async.commit_group;\n");
}
__device__ __forceinline__ void split2(float v, __nv_bfloat16& hi, __nv_bfloat16& lo) {
    hi = __float2bfloat16(v);
    lo = __float2bfloat16(v - __bfloat162float(hi));
}
__device__ __forceinline__ uint32_t smem_u32(const void* p) {
    return (uint32_t)__cvta_generic_to_shared(p);
}

#if TC_OK
__device__ __forceinline__ uint32_t elect_one_pred() {
    uint32_t pred;
    asm volatile(
        "{\n\t.reg .pred p;\n\t"
        "elect.sync _|p, 0xFFFFFFFF;\n\t"
        "selp.b32 %0, 1, 0, p;\n\t}"
        : "=r"(pred));
    return pred;
}
__device__ __forceinline__ void mbar_init(uint32_t mbar, uint32_t cnt) {
    asm volatile("mbarrier.init.shared.b64 [%0], %1;" :: "r"(mbar), "r"(cnt) : "memory");
}
__device__ __forceinline__ void mbar_inval(uint32_t mbar) {
    asm volatile("mbarrier.inval.shared.b64 [%0];" :: "r"(mbar) : "memory");
}
__device__ __forceinline__ void mbar_wait(uint32_t mbar, uint32_t parity) {
    asm volatile(
        "{\n\t.reg .pred P1;\n\t"
        "WAIT_LOOP_%=:\n\t"
        "mbarrier.try_wait.parity.acquire.cta.shared::cta.b64 P1, [%0], %1, 0x989680;\n\t"
        "@P1 bra.uni WAIT_DONE_%=;\n\t"
        "bra.uni WAIT_LOOP_%=;\n\t"
        "WAIT_DONE_%=:\n\t}"
        :: "r"(mbar), "r"(parity) : "memory");
}
__device__ __forceinline__ void tcgen05_commit(uint32_t mbar) {
    asm volatile(
        "tcgen05.commit.cta_group::1.mbarrier::arrive::one.shared::cluster.b64 [%0];"
        :: "r"(mbar) : "memory");
}
__device__ __forceinline__ void fence_proxy_async_cta() {
    asm volatile("fence.proxy.async.shared::cta;" ::: "memory");
}

static constexpr uint64_t SMEM_DESC_BASE_SW128 =
    (uint64_t(2)  << 61) | (uint64_t(1) << 46) | (uint64_t(64) << 32) | (uint64_t(1) << 16);
__device__ __forceinline__ uint64_t make_desc(uint32_t addr) {
    return SMEM_DESC_BASE_SW128 | ((uint64_t)(addr >> 4) & 0x3FFF);
}

// idesc: dtype F32, a/b BF16, N=256, M=128, cta_group::1
static constexpr uint32_t IDESC_F16 =
    (1u << 4) | (1u << 7) | (1u << 10) | ((256u / 8u) << 17) | ((128u / 16u) << 24);

__device__ __forceinline__ void mma_f16_ss(uint32_t d_tmem, uint64_t a_desc,
                                           uint64_t b_desc, uint32_t en) {
    asm volatile(
        "{\n\t.reg .pred p;\n\t"
        "setp.ne.u32 p, %4, 0;\n\t"
        "tcgen05.mma.cta_group::1.kind::f16 [%0], %1, %2, %3, {%5,%5,%5,%5}, p;\n\t}"
        :: "r"(d_tmem), "l"(a_desc), "l"(b_desc), "r"(IDESC_F16), "r"(en), "r"(0u)
        : "memory");
}

#define TC_ALLOC(dst_smem, n) \
    asm volatile("tcgen05.alloc.cta_group::1.sync.aligned.shared::cta.b32 [%0], %1;" \
                 :: "r"(dst_smem), "r"((uint32_t)(n)) : "memory")
#define TC_DEALLOC(tmem, n) \
    asm volatile("tcgen05.dealloc.cta_group::1.sync.aligned.b32 %0, %1;" \
                 :: "r"(tmem), "r"((uint32_t)(n)))
#define TC_FENCE_AFTER()  asm volatile("tcgen05.fence::after_thread_sync;" ::: "memory")
#define TC_FENCE_BEFORE() asm volatile("tcgen05.fence::before_thread_sync;" ::: "memory")
#define TC_WAIT_LD()      asm volatile("tcgen05.wait::ld.sync.aligned;" ::: "memory")

#define TC_LD_X32(r, addr) \
    asm volatile( \
        "tcgen05.ld.sync.aligned.32x32b.x32.b32 " \
        "{%0, %1, %2, %3, %4, %5, %6, %7, " \
        " %8, %9, %10, %11, %12, %13, %14, %15, " \
        " %16, %17, %18, %19, %20, %21, %22, %23, " \
        " %24, %25, %26, %27, %28, %29, %30, %31}, [%32];" \
        : "=r"((r)[0]),  "=r"((r)[1]),  "=r"((r)[2]),  "=r"((r)[3]), \
          "=r"((r)[4]),  "=r"((r)[5]),  "=r"((r)[6]),  "=r"((r)[7]), \
          "=r"((r)[8]),  "=r"((r)[9]),  "=r"((r)[10]), "=r"((r)[11]), \
          "=r"((r)[12]), "=r"((r)[13]), "=r"((r)[14]), "=r"((r)[15]), \
          "=r"((r)[16]), "=r"((r)[17]), "=r"((r)[18]), "=r"((r)[19]), \
          "=r"((r)[20]), "=r"((r)[21]), "=r"((r)[22]), "=r"((r)[23]), \
          "=r"((r)[24]), "=r"((r)[25]), "=r"((r)[26]), "=r"((r)[27]), \
          "=r"((r)[28]), "=r"((r)[29]), "=r"((r)[30]), "=r"((r)[31]) \
        : "r"(addr))
#endif  // TC_OK

__device__ __forceinline__ void mma16816(float c[4], const uint32_t a[4], const uint32_t b[2]) {
    asm volatile(
        "mma.sync.aligned.m16n8k16.row.col.f32.bf16.bf16.f32 "
        "{%0,%1,%2,%3}, {%4,%5,%6,%7}, {%8,%9}, {%0,%1,%2,%3};\n"
        : "+f"(c[0]), "+f"(c[1]), "+f"(c[2]), "+f"(c[3])
        : "r"(a[0]), "r"(a[1]), "r"(a[2]), "r"(a[3]), "r"(b[0]), "r"(b[1]));
}

// ---------------------------------------------------------------------------
// prep kernels
// ---------------------------------------------------------------------------
__global__ void split_z_kernel(const float* __restrict__ koop) {
    __nv_bfloat16* Zh = (__nv_bfloat16*)(g_scratch + OFF_ZH);
    __nv_bfloat16* Zl = (__nv_bfloat16*)(g_scratch + OFF_ZL);
    __shared__ float s[64][65];
    int b = blockIdx.x;
    const float* src = koop + (size_t)b * 4096;
    for (int t = threadIdx.x; t < 4096; t += 256) {
        int l = t >> 6, i = t & 63;
        s[l][i] = src[t];
    }
    __syncthreads();
    for (int t = threadIdx.x; t < 4096; t += 256) {
        int i = t >> 6, l = t & 63;
        float v = s[l][i];
        __nv_bfloat16 h, lo; split2(v, h, lo);
        size_t o = (size_t)(b * 64 + i) * 64 + l;
        Zh[o] = h; Zl[o] = lo;
    }
}

__global__ void split_weight(const float* __restrict__ W, size_t elemOff, int fi) {
    __nv_bfloat16* Wth = (__nv_bfloat16*)(g_scratch + OFF_WTH) + elemOff;
    __nv_bfloat16* Wtl = (__nv_bfloat16*)(g_scratch + OFF_WTL) + elemOff;
    int idx = blockIdx.x * blockDim.x + threadIdx.x;
    if (idx >= fi * 512) return;
    int n = idx / fi, k = idx - n * fi;
    float v = W[(size_t)k * 512 + n];
    __nv_bfloat16 h, lo; split2(v, h, lo);
    Wth[idx] = h; Wtl[idx] = lo;
}

__global__ void transpose_w4(const float* __restrict__ W4, int sel) {
    float* W4t = (float*)(g_scratch + OFF_W4T) + (size_t)sel * 32768;
    int idx = blockIdx.x * blockDim.x + threadIdx.x;
    if (idx >= 64 * 512) return;
    int d = idx >> 9, k = idx & 511;
    W4t[idx] = W4[(size_t)k * 64 + d];
}

// ---------------------------------------------------------------------------
// persistent GEMM, N=512 tiles, K-chunk 32, hi/lo interleaved in SW128 rows
// stage: A 128x128B (16KB) @0, B 512x128B (64KB) @16384; 2 stages
// row layout: slots 0-3 = hi (k 0..31), slots 4-7 = lo (k 0..31)
// ---------------------------------------------------------------------------
static constexpr uint32_t STG_B_OFF = 16384;
static constexpr uint32_t STG_SZ  = 81920;
static constexpr int GEMM_SMEM = 2 * 81920 + 1024;   // 164864 dynamic

#if TC_OK
__device__ __forceinline__ void load_stage(uint32_t tile, int st, int k0,
                                           int rowCTA, int colCTA, int K, int aLD, int aColOff,
                                           const __nv_bfloat16* Ah, const __nv_bfloat16* Al,
                                           const __nv_bfloat16* Bh, const __nv_bfloat16* Bl) {
    const uint32_t base = tile + (uint32_t)st * STG_SZ;
    const int tid = threadIdx.x;
    #pragma unroll
    for (int j = 0; j < 4; ++j) {            // A: 128 rows x 8 slots
        int idx = tid + 256 * j;
        int row = idx >> 3, slot = idx & 7;
        uint32_t boff = (uint32_t)(row * 128 + slot * 16);
        uint32_t sw = boff ^ ((boff >> 3) & 0x70);
        const size_t g = (size_t)(rowCTA + row) * aLD + aColOff + k0 + (slot & 3) * 8;
        cp16(base + sw, (slot < 4 ? Ah : Al) + g);
    }
    #pragma unroll
    for (int j = 0; j < 16; ++j) {           // B: 512 rows x 8 slots
        int idx = tid + 256 * j;
        int row = idx >> 3, slot = idx & 7;
        uint32_t boff = (uint32_t)(row * 128 + slot * 16);
        uint32_t sw = boff ^ ((boff >> 3) & 0x70);
        const size_t g = (size_t)(colCTA + row) * K + k0 + (slot & 3) * 8;
        cp16(base + STG_B_OFF + sw, (slot < 4 ? Bh : Bl) + g);
    }
}

// epilogue of one finished tile (MMA completion already waited)
__device__ __forceinline__ void epilogue_tc(uint32_t tmem, const float* sb,
                                            int rowCTA, int colCTA, int diagMode,
                                            __nv_bfloat16* Ch, __nv_bfloat16* Cl,
                                            const float* W4T, float* dsbuf, float* dtbuf,
                                            int warp, int lane) {
    TC_FENCE_AFTER();
    const int sub = warp & 3;
    const int colbase = (warp >> 2) * 256;
    const int row = rowCTA + sub * 32 + lane;

    if (!diagMode) {
        #pragma unroll
        for (int cc = 0; cc < 8; ++cc) {
            const int c0 = colbase + cc * 32;
            uint32_t r[32];
            TC_LD_X32(r, tmem + (uint32_t)c0);
            TC_WAIT_LD();
            uint32_t ph[16], pl[16];
            #pragma unroll
            for (int c = 0; c < 32; c += 2) {
                float v0 = tanhf(__uint_as_float(r[c])     + sb[c0 + c]);
                float v1 = tanhf(__uint_as_float(r[c + 1]) + sb[c0 + c + 1]);
                __nv_bfloat16 h0, l0, h1, l1;
                split2(v0, h0, l0); split2(v1, h1, l1);
                __nv_bfloat162 th = __halves2bfloat162(h0, h1);
                __nv_bfloat162 tl = __halves2bfloat162(l0, l1);
                ph[c >> 1] = *reinterpret_cast<uint32_t*>(&th);
                pl[c >> 1] = *reinterpret_cast<uint32_t*>(&tl);
            }
            const size_t o = (size_t)row * NW + colCTA + c0;
            uint4* dh = reinterpret_cast<uint4*>(Ch + o);
            uint4* dl = reinterpret_cast<uint4*>(Cl + o);
            #pragma unroll
            for (int q = 0; q < 4; ++q) {
                dh[q] = make_uint4(ph[4 * q], ph[4 * q + 1], ph[4 * q + 2], ph[4 * q + 3]);
                dl[q] = make_uint4(pl[4 * q], pl[4 * q + 1], pl[4 * q + 2], pl[4 * q + 3]);
            }
        }
    } else {
        const int sel = colCTA >> 9;     // 0 = s half, 1 = t half
        const float* w4 = W4T + (size_t)sel * 32768 + (size_t)(row & 63) * 512 + colbase;
        float p = 0.f;
        #pragma unroll
        for (int cc = 0; cc < 8; ++cc) {
            const int c0 = colbase + cc * 32;
            uint32_t r[32];
            TC_LD_X32(r, tmem + (uint32_t)c0);
            TC_WAIT_LD();
            #pragma unroll
            for (int c = 0; c < 32; ++c) {
                float v = tanhf(__uint_as_float(r[c]) + sb[c0 + c]);
                p += v * w4[cc * 32 + c];
            }
        }
        atomicAdd((sel ? dtbuf : dsbuf) + row, p);
    }
    TC_FENCE_BEFORE();
}
#else
__device__ __forceinline__ void load_tiles_fb(__nv_bfloat16* smem, int st, int k0,
                                              int rowCTA, int colCTA, int K, int aLD, int aColOff,
                                              const __nv_bfloat16* Ah, const __nv_bfloat16* Al,
                                              const __nv_bfloat16* Bth, const __nv_bfloat16* Btl) {
    uint32_t sbase = smem_u32(smem);
    #pragma unroll
    for (int it = 0; it < 2; ++it) {
        int idx = it * 256 + threadIdx.x;
        int row = idx >> 2;
        int sc  = (idx & 3) * 8;
        uint32_t o = sbase + (uint32_t)st * (128 * 40 * 2)
                           + (uint32_t)row * (40 * 2) + (uint32_t)sc * 2;
        const size_t ga = (size_t)(rowCTA + row) * aLD + aColOff + k0 + sc;
        const size_t gb = (size_t)(colCTA + row) * K + k0 + sc;
        cp16(o,          Ah  + ga);
        cp16(o + 20480u, Al  + ga);
        cp16(o + 40960u, Bth + gb);
        cp16(o + 61440u, Btl + gb);
    }
}
#endif

__global__ void __launch_bounds__(256, 1)
gemm_p(size_t offAh, size_t offAl, int aLD, int splitA, size_t wElemOff,
       const float* __restrict__ bias_s, const float* __restrict__ bias_t,
       size_t offCh, size_t offCl, int K, int diagMode) {
    const __nv_bfloat16* Ah  = (const __nv_bfloat16*)(g_scratch + offAh);
    const __nv_bfloat16* Al  = (const __nv_bfloat16*)(g_scratch + offAl);
    const __nv_bfloat16* Bth = (const __nv_bfloat16*)(g_scratch + OFF_WTH) + wElemOff;
    const __nv_bfloat16* Btl = (const __nv_bfloat16*)(g_scratch + OFF_WTL) + wElemOff;
    __nv_bfloat16* Ch = (__nv_bfloat16*)(g_scratch + offCh);
    __nv_bfloat16* Cl = (__nv_bfloat16*)(g_scratch + offCl);
    const float* W4T = (const float*)(g_scratch + OFF_W4T);
    float* dsbuf = (float*)(g_scratch + OFF_DS);
    float* dtbuf = (float*)(g_scratch + OFF_DT);

#if TC_OK
    // =======================  persistent tcgen05 path  =======================
    extern __shared__ __align__(16) unsigned char dyn[];
    __shared__ __align__(16) uint32_t s_ctrl[4];     // [0] = tmem base
    __shared__ __align__(16) uint64_t s_mbars[2];    // per-stage-slot commit mbars
    __shared__ float sbias[512];

    const int tid  = threadIdx.x;
    const int warp = tid >> 5, lane = tid & 31;
    const int G = gridDim.x;

    const uint32_t tile = (smem_u32(dyn) + 1023u) & ~1023u;
    const uint32_t ctrl = smem_u32(s_ctrl);
    const uint32_t mbar0 = smem_u32(&s_mbars[0]);

    if (warp == 0) TC_ALLOC(ctrl, 512);
    if (tid == 0) { mbar_init(mbar0, 1); mbar_init(mbar0 + 8, 1); }
    __syncthreads();
    const uint32_t tmem = s_ctrl[0];

    const int nk = K >> 5;                              // K-chunk = 32
    const int ntl = (blockIdx.x < NT2) ? ((NT2 - 1 - blockIdx.x) / G + 1) : 0;
    const long total = (long)ntl * nk;

    // wait for commit of chunk j (j-th commit overall; slot j&1; phase j>>1)
    #define WAIT_COMMIT(j) mbar_wait(mbar0 + 8 * (int)((j) & 1), (uint32_t)(((j) >> 1) & 1))

    // prologue: load chunk 0
    if (ntl > 0) {
        int t0 = blockIdx.x;
        int col0 = (t0 & 1) * 512, row0 = (t0 >> 1) * 128;
        int ao0 = splitA ? col0 : 0;
        load_stage(tile, 0, 0, row0, col0, K, aLD, ao0, Ah, Al, Bth, Btl);
        cp_commit();
    }

    long c = 0;
    int t = blockIdx.x;
    for (int lt = 0; lt < ntl; ++lt, t += G) {
        const int colCTA = (t & 1) * 512;
        const int rowCTA = (t >> 1) * 128;
        const int aColOff = splitA ? colCTA : 0;
        {
            const float* bp = (t & 1) ? bias_t : bias_s;
            sbias[tid] = bp[tid];
            sbias[tid + 256] = bp[tid + 256];
        }

        for (int i = 0; i < nk; ++i, ++c) {
            const int slot = (int)(c & 1);
            if (c + 1 < total) {
                if (c >= 1) WAIT_COMMIT(c - 1);          // frees slot^1, orders MMA
                // prefetch chunk c+1
                int pi = i + 1, prow = rowCTA, pcol = colCTA, pao = aColOff;
                if (pi == nk) {
                    int pt = t + G;
                    pi = 0; pcol = (pt & 1) * 512; prow = (pt >> 1) * 128;
                    pao = splitA ? pcol : 0;
                }
                load_stage(tile, slot ^ 1, pi * 32, prow, pcol, K, aLD, pao, Ah, Al, Bth, Btl);
                cp_commit();
                asm volatile("cp.async.wait_group 1;\n" ::: "memory");  // chunk c ready
            } else {
                asm volatile("cp.async.wait_group 0;\n" ::: "memory");
            }
            fence_proxy_async_cta();
            __syncthreads();

            if (warp == 0 && elect_one_pred()) {
                const uint32_t sa = tile + (uint32_t)slot * STG_SZ;
                const uint64_t dA = make_desc(sa);
                const uint64_t dB = make_desc(sa + STG_B_OFF);
                #pragma unroll
                for (int nh = 0; nh < 2; ++nh) {
                    const uint32_t D = tmem + (uint32_t)(nh * 256);
                    const uint64_t bB = dB + (uint64_t)(nh * 2048);
                    #pragma unroll
                    for (int ks = 0; ks < 2; ++ks) {
                        const uint64_t ko = (uint64_t)(ks * 2);
                        const uint32_t en0 = (i > 0 || ks > 0) ? 1u : 0u;
                        mma_f16_ss(D, dA + ko,     bB + ko,     en0);  // Ah*Bh
                        mma_f16_ss(D, dA + ko,     bB + 4 + ko, 1u);   // Ah*Bl
                        mma_f16_ss(D, dA + 4 + ko, bB + ko,     1u);   // Al*Bh
                    }
                }
                tcgen05_commit(mbar0 + 8 * slot);
            }
        }

        // tile end: wait last chunk's MMA, run epilogue (next tile's chunk-0
        // loads were prefetched above and land during this)
        WAIT_COMMIT(c - 1);
        epilogue_tc(tmem, sbias, rowCTA, colCTA, diagMode, Ch, Cl, W4T,
                    dsbuf, dtbuf, warp, lane);
        __syncthreads();
    }
    #undef WAIT_COMMIT

    __syncthreads();
    if (tid == 0) { mbar_inval(mbar0); mbar_inval(mbar0 + 8); }
    __syncthreads();
    if (warp == 0) TC_DEALLOC(tmem, 512);

#else
    // ============ mma.sync fallback (grid-stride persistent, M128/N256) ======
    extern __shared__ __align__(16) __nv_bfloat16 smem[];
    const int tid  = threadIdx.x;
    const int warp = tid >> 5, lane = tid & 31;
    const int wm = warp & 1, wn = warp >> 1;
    const int g  = lane >> 2, tg = lane & 3;

    for (int t = blockIdx.x; t < NTILES; t += gridDim.x) {
        const int colBase256 = (t & 3) * 256;
        const int rowCTA = (t >> 2) * 128;
        const int aColOff = splitA ? (colBase256 & 512) : 0;

        for (int nh = 0; nh < 2; ++nh) {
            const int colCTA = colBase256 + nh * 128;

            float acc[4][4][4];
            #pragma unroll
            for (int a = 0; a < 4; ++a)
                #pragma unroll
                for (int b = 0; b < 4; ++b)
                    #pragma unroll
                    for (int cc2 = 0; cc2 < 4; ++cc2) acc[a][b][cc2] = 0.f;

            const int nk = K / 32;
            __syncthreads();
            load_tiles_fb(smem, 0, 0, rowCTA, colCTA, K, aLD, aColOff, Ah, Al, Bth, Btl);
            cp_commit();

            for (int kk = 0; kk < nk; ++kk) {
                if (kk + 1 < nk) {
                    load_tiles_fb(smem, (kk + 1) & 1, (kk + 1) * 32, rowCTA, colCTA, K, aLD,
                                  aColOff, Ah, Al, Bth, Btl);
                    cp_commit();
                    asm volatile("cp.async.wait_group 1;\n");
                } else {
                    asm volatile("cp.async.wait_group 0;\n");
                }
                __syncthreads();

                const int st = kk & 1;
                const __nv_bfloat16* pAh = smem + (size_t)st * 128 * 40;
                const __nv_bfloat16* pAl = pAh + 2 * 128 * 40;
                const __nv_bfloat16* pBh = pAh + 4 * 128 * 40;
                const __nv_bfloat16* pBl = pAh + 6 * 128 * 40;

                #pragma unroll
                for (int kh = 0; kh < 2; ++kh) {
                    const int k16 = kh * 16 + 2 * tg;
                    uint32_t afh[4][4], afl[4][4];
                    #pragma unroll
                    for (int mt = 0; mt < 4; ++mt) {
                        const int r0 = (wm * 64 + mt * 16 + g) * 40 + k16;
                        const __nv_bfloat16* p = pAh + r0;
                        const __nv_bfloat16* q = pAl + r0;
                        afh[mt][0] = *(const uint32_t*)(p);
                        afh[mt][1] = *(const uint32_t*)(p + 8 * 40);
                        afh[mt][2] = *(const uint32_t*)(p + 8);
                        afh[mt][3] = *(const uint32_t*)(p + 8 * 40 + 8);
                        afl[mt][0] = *(const uint32_t*)(q);
                        afl[mt][1] = *(const uint32_t*)(q + 8 * 40);
                        afl[mt][2] = *(const uint32_t*)(q + 8);
                        afl[mt][3] = *(const uint32_t*)(q + 8 * 40 + 8);
                    }
                    #pragma unroll
                    for (int nt = 0; nt < 4; ++nt) {
                        const int c0 = (wn * 32 + nt * 8 + g) * 40 + k16;
                        const __nv_bfloat16* pb = pBh + c0;
                        const __nv_bfloat16* qb = pBl + c0;
                        uint32_t bh[2] = { *(const uint32_t*)(pb), *(const uint32_t*)(pb + 8) };
                        uint32_t bl[2] = { *(const uint32_t*)(qb), *(const uint32_t*)(qb + 8) };
                        #pragma unroll
                        for (int mt = 0; mt < 4; ++mt) {
                            mma16816(acc[mt][nt], afh[mt], bh);
                            mma16816(acc[mt][nt], afh[mt], bl);
                            mma16816(acc[mt][nt], afl[mt], bh);
                        }
                    }
                }
                __syncthreads();
            }

            #pragma unroll
            for (int mt = 0; mt < 4; ++mt) {
                const int r0 = rowCTA + wm * 64 + mt * 16 + g;
                #pragma unroll
                for (int nt = 0; nt < 4; ++nt) {
                    const int cc = colCTA + wn * 32 + nt * 8 + 2 * tg;
                    const float bb0 = (cc < 512) ? bias_s[cc] : bias_t[cc - 512];
                    const float bb1 = (cc + 1 < 512) ? bias_s[cc + 1] : bias_t[cc + 1 - 512];
                    #pragma unroll
                    for (int h = 0; h < 2; ++h) {
                        const int r = r0 + h * 8;
                        float v0 = tanhf(acc[mt][nt][2 * h + 0] + bb0);
                        float v1 = tanhf(acc[mt][nt][2 * h + 1] + bb1);
                        if (!diagMode) {
                            __nv_bfloat16 h0, l0, h1, l1;
                            split2(v0, h0, l0); split2(v1, h1, l1);
                            size_t off = (size_t)r * NW + cc;
                            *reinterpret_cast<__nv_bfloat162*>(Ch + off) = __halves2bfloat162(h0, h1);
                            *reinterpret_cast<__nv_bfloat162*>(Cl + off) = __halves2bfloat162(l0, l1);
                        } else {
                            const int sel = (cc >= 512);
                            const float* w4 = W4T + (size_t)sel * 32768 + (size_t)(r & 63) * 512
                                            + (cc - sel * 512);
                            atomicAdd((sel ? dtbuf : dsbuf) + r, v0 * w4[0] + v1 * w4[1]);
                        }
                    }
                }
            }
        }
    }
#endif
}

// out = (x - (dt + b4_t[r%64])) * exp(-(ds + b4_s[r%64]))
__global__ void final_combine2(const float* __restrict__ x,
                               const float* __restrict__ b4s,
                               const float* __restrict__ b4t,
                               float* __restrict__ out) {
    const float* ds = (const float*)(g_scratch + OFF_DS);
    const float* dt = (const float*)(g_scratch + OFF_DT);
    int r = blockIdx.x * blockDim.x + threadIdx.x;
    if (r < R_) {
        int i = r & 63;
        out[r] = (x[r] - (dt[r] + b4t[i])) * expf(-(ds[r] + b4s[i]));
    }
}

// ---------------------------------------------------------------------------
// launch
// ---------------------------------------------------------------------------
extern "C" void kernel_launch(void* const* d_in, const int* in_sizes, int n_in,
                              void* d_out, int out_size) {
    (void)in_sizes; (void)n_in; (void)out_size;
    const float* x    = (const float*)d_in[0];
    const float* koop = (const float*)d_in[1];
    const float* W1[2] = { (const float*)d_in[2],  (const float*)d_in[10] };
    const float* b1[2] = { (const float*)d_in[3],  (const float*)d_in[11] };
    const float* W2[2] = { (const float*)d_in[4],  (const float*)d_in[12] };
    const float* b2[2] = { (const float*)d_in[5],  (const float*)d_in[13] };
    const float* W3[2] = { (const float*)d_in[6],  (const float*)d_in[14] };
    const float* b3[2] = { (const float*)d_in[7],  (const float*)d_in[15] };
    const float* W4[2] = { (const float*)d_in[8],  (const float*)d_in[16] };
    const float* b4[2] = { (const float*)d_in[9],  (const float*)d_in[17] };
    float* out = (float*)d_out;

    cudaFuncSetAttribute((const void*)gemm_p,
                         cudaFuncAttributeMaxDynamicSharedMemorySize, GEMM_SMEM);

    int nsm = 0;
    cudaDeviceGetAttribute(&nsm, cudaDevAttrMultiProcessorCount, 0);
    if (nsm <= 0) nsm = 148;

    // prep
    split_z_kernel<<<B_, 256>>>(koop);
    for (int m = 0; m < 2; ++m) {
        split_weight<<<(512 * 64  + 255) / 256, 256>>>(W1[m], WOFF_1 + (size_t)m * 512 * 64,  64);
        split_weight<<<(512 * 512 + 255) / 256, 256>>>(W2[m], WOFF_2 + (size_t)m * 512 * 512, 512);
        split_weight<<<(512 * 512 + 255) / 256, 256>>>(W3[m], WOFF_3 + (size_t)m * 512 * 512, 512);
        transpose_w4<<<(64 * 512 + 255) / 256, 256>>>(W4[m], m);
    }

    // zero ds/dt accumulators
    void* base = nullptr;
    cudaGetSymbolAddress(&base, g_scratch);
    cudaMemsetAsync((unsigned char*)base + OFF_DS, 0, 2 * SZ_DS, 0);

    // layer 1: Z (K=64) -> H0
    gemm_p<<<nsm, 256, GEMM_SMEM>>>(OFF_ZH, OFF_ZL, 64, 0, WOFF_1,
                                    b1[0], b1[1], OFF_H0H, OFF_H0L, 64, 0);
    // layer 2: H0 -> H1 (block-diagonal via aColOff)
    gemm_p<<<nsm, 256, GEMM_SMEM>>>(OFF_H0H, OFF_H0L, NW, 1, WOFF_2,
                                    b2[0], b2[1], OFF_H1H, OFF_H1L, 512, 0);
    // layer 3: H1 -> diag dots into ds/dt (no C store)
    gemm_p<<<nsm, 256, GEMM_SMEM>>>(OFF_H1H, OFF_H1L, NW, 1, WOFF_3,
                                    b3[0], b3[1], OFF_H0H, OFF_H0L, 512, 1);

    final_combine2<<<R_ / 256, 256>>>(x, b4[0], b4[1], out);
}